// round 1
// baseline (speedup 1.0000x reference)
#include <cuda_runtime.h>
#include <math_constants.h>

// Problem shapes (fixed per reference)
#define D     1024
#define TD    3072          // 3*D
#define BATCH 8
#define SEQ   1024
#define NH    16
#define HK    64            // head dim
#define ROWS  (BATCH*SEQ)   // 8192

// Scratch (device globals: allocation-free per harness rules)
__device__ float g_qkv[(size_t)ROWS * TD];  // 96 MB
__device__ float g_o[(size_t)ROWS * D];     // 32 MB

// ---------------------------------------------------------------------------
// Canonical 128x128x8 fp32 SGEMM, 256 threads, 8x8 per thread.
// A: MxK row-major, B: KxN row-major, C: MxN row-major. M,N mult of 128, K mult of 8.
// ---------------------------------------------------------------------------
__global__ __launch_bounds__(256) void sgemm128(const float* __restrict__ A,
                                                const float* __restrict__ B,
                                                float* __restrict__ C,
                                                int M, int N, int Kd)
{
    __shared__ float As[8][128];   // transposed A tile
    __shared__ float Bs[8][128];

    const int tid   = threadIdx.x;
    const int a_row = tid >> 1;          // 0..127
    const int a_col = (tid & 1) << 2;    // 0 or 4
    const int b_row = tid >> 5;          // 0..7
    const int b_col = (tid & 31) << 2;   // 0..124
    const int ty    = tid >> 4;          // 0..15
    const int tx    = tid & 15;          // 0..15

    const float* Ab = A + (size_t)blockIdx.y * 128 * Kd;
    const float* Bb = B + (size_t)blockIdx.x * 128;

    float acc[8][8];
#pragma unroll
    for (int i = 0; i < 8; i++)
#pragma unroll
        for (int j = 0; j < 8; j++) acc[i][j] = 0.f;

    for (int k0 = 0; k0 < Kd; k0 += 8) {
        float4 av = *(const float4*)(Ab + (size_t)a_row * Kd + k0 + a_col);
        As[a_col + 0][a_row] = av.x;
        As[a_col + 1][a_row] = av.y;
        As[a_col + 2][a_row] = av.z;
        As[a_col + 3][a_row] = av.w;
        *(float4*)&Bs[b_row][b_col] =
            *(const float4*)(Bb + (size_t)(k0 + b_row) * N + b_col);
        __syncthreads();

#pragma unroll
        for (int kk = 0; kk < 8; kk++) {
            float af[8], bf[8];
            *(float4*)&af[0] = *(const float4*)&As[kk][ty * 8];
            *(float4*)&af[4] = *(const float4*)&As[kk][ty * 8 + 4];
            *(float4*)&bf[0] = *(const float4*)&Bs[kk][tx * 8];
            *(float4*)&bf[4] = *(const float4*)&Bs[kk][tx * 8 + 4];
#pragma unroll
            for (int i = 0; i < 8; i++)
#pragma unroll
                for (int j = 0; j < 8; j++)
                    acc[i][j] = fmaf(af[i], bf[j], acc[i][j]);
        }
        __syncthreads();
    }

    float* Cb = C + (size_t)(blockIdx.y * 128 + ty * 8) * N + blockIdx.x * 128 + tx * 8;
#pragma unroll
    for (int i = 0; i < 8; i++) {
        *(float4*)(Cb + (size_t)i * N)     = make_float4(acc[i][0], acc[i][1], acc[i][2], acc[i][3]);
        *(float4*)(Cb + (size_t)i * N + 4) = make_float4(acc[i][4], acc[i][5], acc[i][6], acc[i][7]);
    }
}

// ---------------------------------------------------------------------------
// Flash attention (causal, fp32, online softmax).
// QKV layout per reference: qkv[(b*SEQ+m)*TD + h*192 + {0..63=Q, 64..127=K, 128..191=V}]
// Block: 64 Q rows per block, 256 threads = 64 rows x 4 col-segments of 16.
// Smem: sQ[64][64], sKT[64][68] (kk-major, padded), sV[64][64], sP[64][68].
// ---------------------------------------------------------------------------
#define SMEM_FLOATS (4096 + 4352 + 4096 + 4352)   // 16896 floats = 67584 B

__global__ __launch_bounds__(256) void flash_attn(const float* __restrict__ qkv,
                                                  float* __restrict__ o)
{
    extern __shared__ float sm[];
    float* sQ  = sm;                 // [row][kk]   64*64
    float* sKT = sm + 4096;          // [kk][col]   64*68 (pad 68)
    float* sV  = sKT + 4352;         // [col][k]    64*64
    float* sP  = sV + 4096;          // [row][col]  64*68 (pad 68)

    const int tid = threadIdx.x;
    const int b   = blockIdx.y >> 4;
    const int h   = blockIdx.y & 15;
    const int qm0 = blockIdx.x * 64;

    const float* base = qkv + (size_t)b * SEQ * TD + h * (3 * HK);

    const int row = tid >> 2;          // 0..63
    const int c0  = (tid & 3) << 4;    // 0,16,32,48

    // Load Q tile once
    for (int idx = tid; idx < 1024; idx += 256) {
        int r = idx >> 4, c4 = (idx & 15) << 2;
        *(float4*)&sQ[r * 64 + c4] = *(const float4*)(base + (size_t)(qm0 + r) * TD + c4);
    }

    float m_i = -CUDART_INF_F, l_i = 0.f;
    float acc[16];
#pragma unroll
    for (int j = 0; j < 16; j++) acc[j] = 0.f;

    const int qrow = qm0 + row;

    for (int jn0 = 0; jn0 <= qm0; jn0 += 64) {
        __syncthreads();   // previous iter done with sKT/sV; also guards sQ on iter 0
        // Load K (transposed to kk-major) and V tiles
        for (int idx = tid; idx < 1024; idx += 256) {
            int col = idx >> 4, k4 = (idx & 15) << 2;
            const float* rp = base + (size_t)(jn0 + col) * TD;
            float4 kv = *(const float4*)(rp + HK + k4);
            sKT[(k4 + 0) * 68 + col] = kv.x;
            sKT[(k4 + 1) * 68 + col] = kv.y;
            sKT[(k4 + 2) * 68 + col] = kv.z;
            sKT[(k4 + 3) * 68 + col] = kv.w;
            *(float4*)&sV[col * 64 + k4] = *(const float4*)(rp + 2 * HK + k4);
        }
        __syncthreads();

        // S = Q K^T for this thread's (row, 16 cols)
        float s[16];
#pragma unroll
        for (int j = 0; j < 16; j++) s[j] = 0.f;
#pragma unroll 8
        for (int kk = 0; kk < 64; kk++) {
            float q = sQ[row * 64 + kk];
            const float* kr = &sKT[kk * 68 + c0];
#pragma unroll
            for (int j4 = 0; j4 < 16; j4 += 4) {
                float4 kf = *(const float4*)(kr + j4);
                s[j4 + 0] = fmaf(q, kf.x, s[j4 + 0]);
                s[j4 + 1] = fmaf(q, kf.y, s[j4 + 1]);
                s[j4 + 2] = fmaf(q, kf.z, s[j4 + 2]);
                s[j4 + 3] = fmaf(q, kf.w, s[j4 + 3]);
            }
        }

        const bool diag = (jn0 == qm0);
#pragma unroll
        for (int j = 0; j < 16; j++) {
            s[j] *= 0.125f;   // 1/sqrt(64)
            if (diag && (jn0 + c0 + j) > qrow) s[j] = -CUDART_INF_F;
        }

        // Row max across 16 local cols, then across the 4 threads of this row
        float mloc = s[0];
#pragma unroll
        for (int j = 1; j < 16; j++) mloc = fmaxf(mloc, s[j]);
        mloc = fmaxf(mloc, __shfl_xor_sync(0xffffffffu, mloc, 1));
        mloc = fmaxf(mloc, __shfl_xor_sync(0xffffffffu, mloc, 2));
        float m_new = fmaxf(m_i, mloc);
        float alpha = __expf(m_i - m_new);   // m_i=-inf first iter -> 0

        float psum = 0.f;
#pragma unroll
        for (int j = 0; j < 16; j++) {
            float p = __expf(s[j] - m_new);  // masked: exp(-inf)=0
            psum += p;
            sP[row * 68 + c0 + j] = p;
        }
        psum += __shfl_xor_sync(0xffffffffu, psum, 1);
        psum += __shfl_xor_sync(0xffffffffu, psum, 2);
        l_i = l_i * alpha + psum;
        m_i = m_new;
#pragma unroll
        for (int j = 0; j < 16; j++) acc[j] *= alpha;

        __syncthreads();   // sP visible to all threads of the row

        // acc += P @ V  (this thread: row, k-range c0..c0+15)
#pragma unroll 4
        for (int col = 0; col < 64; col++) {
            float pv = sP[row * 68 + col];
            const float* vr = &sV[col * 64 + c0];
#pragma unroll
            for (int j4 = 0; j4 < 16; j4 += 4) {
                float4 vf = *(const float4*)(vr + j4);
                acc[j4 + 0] = fmaf(pv, vf.x, acc[j4 + 0]);
                acc[j4 + 1] = fmaf(pv, vf.y, acc[j4 + 1]);
                acc[j4 + 2] = fmaf(pv, vf.z, acc[j4 + 2]);
                acc[j4 + 3] = fmaf(pv, vf.w, acc[j4 + 3]);
            }
        }
    }

    // Normalize and store O in [b*SEQ+m, h*64+k] layout (matches reference transpose)
    float inv = 1.f / l_i;
    float* op = o + (size_t)(b * SEQ + qrow) * D + h * HK + c0;
#pragma unroll
    for (int j4 = 0; j4 < 16; j4 += 4)
        *(float4*)(op + j4) = make_float4(acc[j4 + 0] * inv, acc[j4 + 1] * inv,
                                          acc[j4 + 2] * inv, acc[j4 + 3] * inv);
}

// ---------------------------------------------------------------------------
extern "C" void kernel_launch(void* const* d_in, const int* in_sizes, int n_in,
                              void* d_out, int out_size)
{
    const float* x  = (const float*)d_in[0];   // [8,1024,1024]
    const float* Pi = (const float*)d_in[1];   // [1024,3072]
    const float* Po = (const float*)d_in[2];   // [1024,1024]
    float* y = (float*)d_out;                  // [8,1024,1024]

    float *qkv, *ob;
    cudaGetSymbolAddress((void**)&qkv, g_qkv);
    cudaGetSymbolAddress((void**)&ob,  g_o);

    cudaFuncSetAttribute(flash_attn, cudaFuncAttributeMaxDynamicSharedMemorySize,
                         SMEM_FLOATS * 4);

    // 1) QKV projection: [8192,1024] @ [1024,3072]
    sgemm128<<<dim3(TD / 128, ROWS / 128), 256>>>(x, Pi, qkv, ROWS, TD, D);
    // 2) Causal flash attention per (b,h), 64-row Q tiles
    flash_attn<<<dim3(SEQ / 64, BATCH * NH), 256, SMEM_FLOATS * 4>>>(qkv, ob);
    // 3) Output projection: [8192,1024] @ [1024,1024]
    sgemm128<<<dim3(D / 128, ROWS / 128), 256>>>(ob, Po, y, ROWS, D, D);
}

// round 11
// speedup vs baseline: 3.9341x; 3.9341x over previous
#include <cuda_runtime.h>
#include <math_constants.h>

#define D     1024
#define TD    3072
#define BATCH 8
#define SEQ   1024
#define NH    16
#define HK    64
#define ROWS  (BATCH*SEQ)   // 8192

// Scratch (device globals: allocation-free)
__device__ float g_qkv[(size_t)ROWS * TD];  // 96 MB
__device__ float g_o[(size_t)ROWS * D];     // 32 MB

__device__ __forceinline__ float tf32r(float x) {
    unsigned u; asm("cvt.rna.tf32.f32 %0, %1;" : "=r"(u) : "f"(x));
    return __uint_as_float(u);
}
__device__ __forceinline__ unsigned f2u(float x) { return __float_as_uint(x); }

// m16n8k4 tf32 mma, D += A*B.  [g=lane>>2, t=lane&3]
// A frag (16x4): a0=(row g,  col t), a1=(row g+8, col t)   -- dimension-forced
// B frag (4x8):  b0=(row k=t, col n=g)
// C frag (16x8): x=(g,2t) y=(g,2t+1) z=(g+8,2t) w=(g+8,2t+1)
__device__ __forceinline__ void mma_tf32_k4(float4& d, unsigned a0, unsigned a1,
                                            unsigned b0) {
    asm volatile(
        "mma.sync.aligned.m16n8k4.row.col.f32.tf32.tf32.f32 "
        "{%0,%1,%2,%3}, {%4,%5}, {%6}, {%0,%1,%2,%3};"
        : "+f"(d.x), "+f"(d.y), "+f"(d.z), "+f"(d.w)
        : "r"(a0), "r"(a1), "r"(b0));
}

// ---------------------------------------------------------------------------
// tf32 GEMM: C[M,N] = A[M,K] @ B[K,N], 128x128 tile, K-chunk 32.
// 256 threads = 8 warps (2 m x 4 n), each warp 64x32 via m16n8k4 tiles.
// Tiles: sA 128 rows x 32 cols (stride 36 >= 32: legal), sB 32 x 128 (stride 136).
// Register-staged prefetch hides global latency behind the MMA loop.
// ---------------------------------------------------------------------------
#define KS 32
#define SAS 36
#define SBS 136

__global__ __launch_bounds__(256) void gemm_tf32(const float* __restrict__ A,
                                                 const float* __restrict__ B,
                                                 float* __restrict__ C,
                                                 int M, int N, int Kd)
{
    __shared__ float sA[128 * SAS];  // [m][k]
    __shared__ float sB[KS * SBS];   // [k][n]

    const int tid  = threadIdx.x;
    const int lane = tid & 31, wid = tid >> 5;
    const int wm = (wid & 1) * 64, wn = (wid >> 1) * 32;
    const int g = lane >> 2, t = lane & 3;

    const float* Ab = A + (size_t)blockIdx.y * 128 * Kd;
    const float* Bb = B + (size_t)blockIdx.x * 128;

    float4 acc[4][4];
#pragma unroll
    for (int i = 0; i < 4; i++)
#pragma unroll
        for (int j = 0; j < 4; j++) acc[i][j] = make_float4(0.f, 0.f, 0.f, 0.f);

    float4 pa[4], pb[4];
#pragma unroll
    for (int it = 0; it < 4; it++) {
        int idx = tid + it * 256;
        int r = idx >> 3, c = (idx & 7) << 2;
        pa[it] = *(const float4*)(Ab + (size_t)r * Kd + c);
        int r2 = idx >> 5, c2 = (idx & 31) << 2;
        pb[it] = *(const float4*)(Bb + (size_t)r2 * N + c2);
    }

    for (int k0 = 0; k0 < Kd; k0 += KS) {
#pragma unroll
        for (int it = 0; it < 4; it++) {
            int idx = tid + it * 256;
            int r = idx >> 3, c = (idx & 7) << 2;
            sA[r * SAS + c + 0] = tf32r(pa[it].x);
            sA[r * SAS + c + 1] = tf32r(pa[it].y);
            sA[r * SAS + c + 2] = tf32r(pa[it].z);
            sA[r * SAS + c + 3] = tf32r(pa[it].w);
            int r2 = idx >> 5, c2 = (idx & 31) << 2;
            sB[r2 * SBS + c2 + 0] = tf32r(pb[it].x);
            sB[r2 * SBS + c2 + 1] = tf32r(pb[it].y);
            sB[r2 * SBS + c2 + 2] = tf32r(pb[it].z);
            sB[r2 * SBS + c2 + 3] = tf32r(pb[it].w);
        }
        __syncthreads();

        const int kn = k0 + KS;
        if (kn < Kd) {
#pragma unroll
            for (int it = 0; it < 4; it++) {
                int idx = tid + it * 256;
                int r = idx >> 3, c = (idx & 7) << 2;
                pa[it] = *(const float4*)(Ab + (size_t)r * Kd + kn + c);
                int r2 = idx >> 5, c2 = (idx & 31) << 2;
                pb[it] = *(const float4*)(Bb + (size_t)(kn + r2) * N + c2);
            }
        }

#pragma unroll
        for (int kk = 0; kk < KS; kk += 4) {
            unsigned a0[4], a1[4];
#pragma unroll
            for (int mt = 0; mt < 4; mt++) {
                int r = wm + mt * 16;
                a0[mt] = f2u(sA[(r + g)     * SAS + kk + t]);
                a1[mt] = f2u(sA[(r + g + 8) * SAS + kk + t]);
            }
#pragma unroll
            for (int nt = 0; nt < 4; nt++) {
                unsigned b0 = f2u(sB[(kk + t) * SBS + wn + nt * 8 + g]);
#pragma unroll
                for (int mt = 0; mt < 4; mt++)
                    mma_tf32_k4(acc[mt][nt], a0[mt], a1[mt], b0);
            }
        }
        __syncthreads();
    }

#pragma unroll
    for (int mt = 0; mt < 4; mt++) {
        int r0 = blockIdx.y * 128 + wm + mt * 16 + g;
#pragma unroll
        for (int nt = 0; nt < 4; nt++) {
            int c = blockIdx.x * 128 + wn + nt * 8 + t * 2;
            *(float2*)(C + (size_t)r0 * N + c)       = make_float2(acc[mt][nt].x, acc[mt][nt].y);
            *(float2*)(C + (size_t)(r0 + 8) * N + c) = make_float2(acc[mt][nt].z, acc[mt][nt].w);
        }
    }
}

// ---------------------------------------------------------------------------
// tf32 flash attention (causal). 128 threads = 4 warps; 64 Q rows per block,
// each warp owns 16 rows x full 64 cols (softmax fully intra-warp).
// FIX vs R2-R7: sQ/sK strides were 36 for 64-wide tiles (row aliasing!) —
// now 68, matching the always-correct sV/sP.
// ---------------------------------------------------------------------------
#define SQS 68
#define SKS 68
#define SVS 68
#define SPS 68
#define ATTN_SMEM ((64*SQS + 64*SKS + 64*SVS + 64*SPS) * 4)   // 69632 B

__global__ __launch_bounds__(128) void flash_tf32(const float* __restrict__ qkv,
                                                  float* __restrict__ o)
{
    extern __shared__ float sm[];
    float* sQ = sm;                   // [row][hk]  64 x SQS
    float* sK = sQ + 64 * SQS;        // [kv][hk]   64 x SKS
    float* sV = sK + 64 * SKS;        // [kv][hk]   64 x SVS
    float* sP = sV + 64 * SVS;        // [row][kv]  64 x SPS

    const int tid  = threadIdx.x;
    const int lane = tid & 31, w = tid >> 5;
    const int g = lane >> 2, t = lane & 3;
    const int b = blockIdx.y >> 4, h = blockIdx.y & 15;
    const int qm0 = blockIdx.x * 64;
    const float* base = qkv + (size_t)b * SEQ * TD + h * (3 * HK);

    // Q tile 64x64 -> smem (tf32)
    for (int idx = tid; idx < 64 * 16; idx += 128) {
        int r = idx >> 4, c = (idx & 15) << 2;
        float4 v = *(const float4*)(base + (size_t)(qm0 + r) * TD + c);
        sQ[r * SQS + c + 0] = tf32r(v.x);
        sQ[r * SQS + c + 1] = tf32r(v.y);
        sQ[r * SQS + c + 2] = tf32r(v.z);
        sQ[r * SQS + c + 3] = tf32r(v.w);
    }

    float4 oacc[8];
#pragma unroll
    for (int nt = 0; nt < 8; nt++) oacc[nt] = make_float4(0.f, 0.f, 0.f, 0.f);
    float m0 = -CUDART_INF_F, m1 = -CUDART_INF_F, l0 = 0.f, l1 = 0.f;
    const int rloc = w * 16;
    const int row0 = qm0 + rloc + g;   // rows for (x,y)
    const int row1 = row0 + 8;         // rows for (z,w)

    for (int j0 = 0; j0 <= qm0; j0 += 64) {
        __syncthreads();
        for (int idx = tid; idx < 64 * 16; idx += 128) {   // K,V tiles
            int r = idx >> 4, c = (idx & 15) << 2;
            const float* rp = base + (size_t)(j0 + r) * TD;
            float4 kv = *(const float4*)(rp + HK + c);
            sK[r * SKS + c + 0] = tf32r(kv.x);
            sK[r * SKS + c + 1] = tf32r(kv.y);
            sK[r * SKS + c + 2] = tf32r(kv.z);
            sK[r * SKS + c + 3] = tf32r(kv.w);
            float4 vv = *(const float4*)(rp + 2 * HK + c);
            sV[r * SVS + c + 0] = tf32r(vv.x);
            sV[r * SVS + c + 1] = tf32r(vv.y);
            sV[r * SVS + c + 2] = tf32r(vv.z);
            sV[r * SVS + c + 3] = tf32r(vv.w);
        }
        __syncthreads();

        // S = Q @ K^T  (this warp: 16 rows x 64 cols)
        float4 s[8];
#pragma unroll
        for (int nt = 0; nt < 8; nt++) s[nt] = make_float4(0.f, 0.f, 0.f, 0.f);
#pragma unroll
        for (int kk = 0; kk < 64; kk += 4) {
            unsigned a0 = f2u(sQ[(rloc + g)     * SQS + kk + t]);
            unsigned a1 = f2u(sQ[(rloc + g + 8) * SQS + kk + t]);
#pragma unroll
            for (int nt = 0; nt < 8; nt++) {
                unsigned b0 = f2u(sK[(nt * 8 + g) * SKS + kk + t]);
                mma_tf32_k4(s[nt], a0, a1, b0);
            }
        }

        const bool diag = (j0 == qm0);
        float mx0 = -CUDART_INF_F, mx1 = -CUDART_INF_F;
#pragma unroll
        for (int nt = 0; nt < 8; nt++) {
            int c = j0 + nt * 8 + t * 2;
            s[nt].x *= 0.125f; s[nt].y *= 0.125f;
            s[nt].z *= 0.125f; s[nt].w *= 0.125f;
            if (diag) {
                if (c     > row0) s[nt].x = -CUDART_INF_F;
                if (c + 1 > row0) s[nt].y = -CUDART_INF_F;
                if (c     > row1) s[nt].z = -CUDART_INF_F;
                if (c + 1 > row1) s[nt].w = -CUDART_INF_F;
            }
            mx0 = fmaxf(mx0, fmaxf(s[nt].x, s[nt].y));
            mx1 = fmaxf(mx1, fmaxf(s[nt].z, s[nt].w));
        }
        mx0 = fmaxf(mx0, __shfl_xor_sync(0xffffffffu, mx0, 1));
        mx0 = fmaxf(mx0, __shfl_xor_sync(0xffffffffu, mx0, 2));
        mx1 = fmaxf(mx1, __shfl_xor_sync(0xffffffffu, mx1, 1));
        mx1 = fmaxf(mx1, __shfl_xor_sync(0xffffffffu, mx1, 2));
        float nm0 = fmaxf(m0, mx0), nm1 = fmaxf(m1, mx1);
        float al0 = __expf(m0 - nm0), al1 = __expf(m1 - nm1);

        float ps0 = 0.f, ps1 = 0.f;
#pragma unroll
        for (int nt = 0; nt < 8; nt++) {
            float p00 = __expf(s[nt].x - nm0), p01 = __expf(s[nt].y - nm0);
            float p10 = __expf(s[nt].z - nm1), p11 = __expf(s[nt].w - nm1);
            ps0 += p00 + p01; ps1 += p10 + p11;
            *(float2*)&sP[(rloc + g)     * SPS + nt * 8 + t * 2] = make_float2(tf32r(p00), tf32r(p01));
            *(float2*)&sP[(rloc + g + 8) * SPS + nt * 8 + t * 2] = make_float2(tf32r(p10), tf32r(p11));
        }
        ps0 += __shfl_xor_sync(0xffffffffu, ps0, 1);
        ps0 += __shfl_xor_sync(0xffffffffu, ps0, 2);
        ps1 += __shfl_xor_sync(0xffffffffu, ps1, 1);
        ps1 += __shfl_xor_sync(0xffffffffu, ps1, 2);
        l0 = l0 * al0 + ps0; l1 = l1 * al1 + ps1;
        m0 = nm0; m1 = nm1;
#pragma unroll
        for (int nt = 0; nt < 8; nt++) {
            oacc[nt].x *= al0; oacc[nt].y *= al0;
            oacc[nt].z *= al1; oacc[nt].w *= al1;
        }
        __syncwarp();

        // O += P @ V (per-warp sP stripe; V is block-shared)
#pragma unroll
        for (int kk = 0; kk < 64; kk += 4) {
            unsigned a0 = f2u(sP[(rloc + g)     * SPS + kk + t]);
            unsigned a1 = f2u(sP[(rloc + g + 8) * SPS + kk + t]);
#pragma unroll
            for (int nt = 0; nt < 8; nt++) {
                unsigned b0 = f2u(sV[(kk + t) * SVS + nt * 8 + g]);
                mma_tf32_k4(oacc[nt], a0, a1, b0);
            }
        }
    }

    const float inv0 = 1.f / l0, inv1 = 1.f / l1;
    float* op = o + (size_t)(b * SEQ + row0) * D + h * HK;
#pragma unroll
    for (int nt = 0; nt < 8; nt++) {
        *(float2*)(op + nt * 8 + t * 2) =
            make_float2(oacc[nt].x * inv0, oacc[nt].y * inv0);
        *(float2*)(op + (size_t)8 * D + nt * 8 + t * 2) =
            make_float2(oacc[nt].z * inv1, oacc[nt].w * inv1);
    }
}

// ---------------------------------------------------------------------------
extern "C" void kernel_launch(void* const* d_in, const int* in_sizes, int n_in,
                              void* d_out, int out_size)
{
    const float* x  = (const float*)d_in[0];
    const float* Pi = (const float*)d_in[1];
    const float* Po = (const float*)d_in[2];
    float* y = (float*)d_out;

    float *qkv, *ob;
    cudaGetSymbolAddress((void**)&qkv, g_qkv);
    cudaGetSymbolAddress((void**)&ob,  g_o);

    cudaFuncSetAttribute(flash_tf32, cudaFuncAttributeMaxDynamicSharedMemorySize,
                         ATTN_SMEM);

    gemm_tf32<<<dim3(TD / 128, ROWS / 128), 256>>>(x, Pi, qkv, ROWS, TD, D);
    flash_tf32<<<dim3(SEQ / 64, BATCH * NH), 128, ATTN_SMEM>>>(qkv, ob);
    gemm_tf32<<<dim3(D / 128, ROWS / 128), 256>>>(ob, Po, y, ROWS, D, D);
}

// round 12
// speedup vs baseline: 5.2644x; 1.3381x over previous
#include <cuda_runtime.h>
#include <math_constants.h>

#define D     1024
#define TD    3072
#define BATCH 8
#define SEQ   1024
#define NH    16
#define HK    64
#define ROWS  (BATCH*SEQ)   // 8192

// Scratch (device globals: allocation-free)
__device__ float g_qkv[(size_t)ROWS * TD];  // 96 MB
__device__ float g_o[(size_t)ROWS * D];     // 32 MB

__device__ __forceinline__ float tf32r(float x) {
    unsigned u; asm("cvt.rna.tf32.f32 %0, %1;" : "=r"(u) : "f"(x));
    return __uint_as_float(u);
}
__device__ __forceinline__ unsigned f2u(float x) { return __float_as_uint(x); }

// m16n8k8 tf32 mma, D += A*B.  [g=lane>>2, t=lane&3]
// A frag (16x8): a0=(g,t) a1=(g+8,t) a2=(g,t+4) a3=(g+8,t+4)
// B frag (8x8):  b0=(k=t,n=g) b1=(k=t+4,n=g)
// C frag (16x8): x=(g,2t) y=(g,2t+1) z=(g+8,2t) w=(g+8,2t+1)   [validated in R11]
__device__ __forceinline__ void mma_tf32_k8(float4& d, unsigned a0, unsigned a1,
                                            unsigned a2, unsigned a3,
                                            unsigned b0, unsigned b1) {
    asm volatile(
        "mma.sync.aligned.m16n8k8.row.col.f32.tf32.tf32.f32 "
        "{%0,%1,%2,%3}, {%4,%5,%6,%7}, {%8,%9}, {%0,%1,%2,%3};"
        : "+f"(d.x), "+f"(d.y), "+f"(d.z), "+f"(d.w)
        : "r"(a0), "r"(a1), "r"(a2), "r"(a3), "r"(b0), "r"(b1));
}

// ---------------------------------------------------------------------------
// tf32 GEMM: C[M,N] = A[M,K] @ B[K,N], 128x128 tile, K-chunk 32.
// 256 threads = 8 warps (2 m x 4 n), each warp 64x32 via m16n8k8 tiles.
// Register-staged prefetch hides global latency behind the MMA loop.
// ---------------------------------------------------------------------------
#define KS 32
#define SAS 36
#define SBS 136

__global__ __launch_bounds__(256) void gemm_tf32(const float* __restrict__ A,
                                                 const float* __restrict__ B,
                                                 float* __restrict__ C,
                                                 int M, int N, int Kd)
{
    __shared__ float sA[128 * SAS];  // [m][k]
    __shared__ float sB[KS * SBS];   // [k][n]

    const int tid  = threadIdx.x;
    const int lane = tid & 31, wid = tid >> 5;
    const int wm = (wid & 1) * 64, wn = (wid >> 1) * 32;
    const int g = lane >> 2, t = lane & 3;

    const float* Ab = A + (size_t)blockIdx.y * 128 * Kd;
    const float* Bb = B + (size_t)blockIdx.x * 128;

    float4 acc[4][4];
#pragma unroll
    for (int i = 0; i < 4; i++)
#pragma unroll
        for (int j = 0; j < 4; j++) acc[i][j] = make_float4(0.f, 0.f, 0.f, 0.f);

    float4 pa[4], pb[4];
#pragma unroll
    for (int it = 0; it < 4; it++) {
        int idx = tid + it * 256;
        int r = idx >> 3, c = (idx & 7) << 2;
        pa[it] = *(const float4*)(Ab + (size_t)r * Kd + c);
        int r2 = idx >> 5, c2 = (idx & 31) << 2;
        pb[it] = *(const float4*)(Bb + (size_t)r2 * N + c2);
    }

    for (int k0 = 0; k0 < Kd; k0 += KS) {
#pragma unroll
        for (int it = 0; it < 4; it++) {
            int idx = tid + it * 256;
            int r = idx >> 3, c = (idx & 7) << 2;
            sA[r * SAS + c + 0] = tf32r(pa[it].x);
            sA[r * SAS + c + 1] = tf32r(pa[it].y);
            sA[r * SAS + c + 2] = tf32r(pa[it].z);
            sA[r * SAS + c + 3] = tf32r(pa[it].w);
            int r2 = idx >> 5, c2 = (idx & 31) << 2;
            sB[r2 * SBS + c2 + 0] = tf32r(pb[it].x);
            sB[r2 * SBS + c2 + 1] = tf32r(pb[it].y);
            sB[r2 * SBS + c2 + 2] = tf32r(pb[it].z);
            sB[r2 * SBS + c2 + 3] = tf32r(pb[it].w);
        }
        __syncthreads();

        const int kn = k0 + KS;
        if (kn < Kd) {
#pragma unroll
            for (int it = 0; it < 4; it++) {
                int idx = tid + it * 256;
                int r = idx >> 3, c = (idx & 7) << 2;
                pa[it] = *(const float4*)(Ab + (size_t)r * Kd + kn + c);
                int r2 = idx >> 5, c2 = (idx & 31) << 2;
                pb[it] = *(const float4*)(Bb + (size_t)(kn + r2) * N + c2);
            }
        }

#pragma unroll
        for (int kk = 0; kk < KS; kk += 8) {
            unsigned a[4][4];
#pragma unroll
            for (int mt = 0; mt < 4; mt++) {
                int r = wm + mt * 16;
                a[mt][0] = f2u(sA[(r + g)     * SAS + kk + t]);
                a[mt][1] = f2u(sA[(r + g + 8) * SAS + kk + t]);
                a[mt][2] = f2u(sA[(r + g)     * SAS + kk + t + 4]);
                a[mt][3] = f2u(sA[(r + g + 8) * SAS + kk + t + 4]);
            }
#pragma unroll
            for (int nt = 0; nt < 4; nt++) {
                unsigned b0 = f2u(sB[(kk + t)     * SBS + wn + nt * 8 + g]);
                unsigned b1 = f2u(sB[(kk + t + 4) * SBS + wn + nt * 8 + g]);
#pragma unroll
                for (int mt = 0; mt < 4; mt++)
                    mma_tf32_k8(acc[mt][nt], a[mt][0], a[mt][1], a[mt][2], a[mt][3], b0, b1);
            }
        }
        __syncthreads();
    }

#pragma unroll
    for (int mt = 0; mt < 4; mt++) {
        int r0 = blockIdx.y * 128 + wm + mt * 16 + g;
#pragma unroll
        for (int nt = 0; nt < 4; nt++) {
            int c = blockIdx.x * 128 + wn + nt * 8 + t * 2;
            *(float2*)(C + (size_t)r0 * N + c)       = make_float2(acc[mt][nt].x, acc[mt][nt].y);
            *(float2*)(C + (size_t)(r0 + 8) * N + c) = make_float2(acc[mt][nt].z, acc[mt][nt].w);
        }
    }
}

// ---------------------------------------------------------------------------
// tf32 flash attention (causal). 128 threads = 4 warps; 64 Q rows per block,
// each warp owns 16 rows x full 64 cols (softmax fully intra-warp).
// Strides 68 everywhere (R11-validated).
// ---------------------------------------------------------------------------
#define SQS 68
#define SKS 68
#define SVS 68
#define SPS 68
#define ATTN_SMEM ((64*SQS + 64*SKS + 64*SVS + 64*SPS) * 4)   // 69632 B

__global__ __launch_bounds__(128) void flash_tf32(const float* __restrict__ qkv,
                                                  float* __restrict__ o)
{
    extern __shared__ float sm[];
    float* sQ = sm;                   // [row][hk]  64 x SQS
    float* sK = sQ + 64 * SQS;        // [kv][hk]   64 x SKS
    float* sV = sK + 64 * SKS;        // [kv][hk]   64 x SVS
    float* sP = sV + 64 * SVS;        // [row][kv]  64 x SPS

    const int tid  = threadIdx.x;
    const int lane = tid & 31, w = tid >> 5;
    const int g = lane >> 2, t = lane & 3;
    const int b = blockIdx.y >> 4, h = blockIdx.y & 15;
    const int qm0 = blockIdx.x * 64;
    const float* base = qkv + (size_t)b * SEQ * TD + h * (3 * HK);

    // Q tile 64x64 -> smem (tf32)
    for (int idx = tid; idx < 64 * 16; idx += 128) {
        int r = idx >> 4, c = (idx & 15) << 2;
        float4 v = *(const float4*)(base + (size_t)(qm0 + r) * TD + c);
        sQ[r * SQS + c + 0] = tf32r(v.x);
        sQ[r * SQS + c + 1] = tf32r(v.y);
        sQ[r * SQS + c + 2] = tf32r(v.z);
        sQ[r * SQS + c + 3] = tf32r(v.w);
    }

    float4 oacc[8];
#pragma unroll
    for (int nt = 0; nt < 8; nt++) oacc[nt] = make_float4(0.f, 0.f, 0.f, 0.f);
    float m0 = -CUDART_INF_F, m1 = -CUDART_INF_F, l0 = 0.f, l1 = 0.f;
    const int rloc = w * 16;
    const int row0 = qm0 + rloc + g;   // rows for (x,y)
    const int row1 = row0 + 8;         // rows for (z,w)

    for (int j0 = 0; j0 <= qm0; j0 += 64) {
        __syncthreads();
        for (int idx = tid; idx < 64 * 16; idx += 128) {   // K,V tiles
            int r = idx >> 4, c = (idx & 15) << 2;
            const float* rp = base + (size_t)(j0 + r) * TD;
            float4 kv = *(const float4*)(rp + HK + c);
            sK[r * SKS + c + 0] = tf32r(kv.x);
            sK[r * SKS + c + 1] = tf32r(kv.y);
            sK[r * SKS + c + 2] = tf32r(kv.z);
            sK[r * SKS + c + 3] = tf32r(kv.w);
            float4 vv = *(const float4*)(rp + 2 * HK + c);
            sV[r * SVS + c + 0] = tf32r(vv.x);
            sV[r * SVS + c + 1] = tf32r(vv.y);
            sV[r * SVS + c + 2] = tf32r(vv.z);
            sV[r * SVS + c + 3] = tf32r(vv.w);
        }
        __syncthreads();

        // S = Q @ K^T  (this warp: 16 rows x 64 cols)
        float4 s[8];
#pragma unroll
        for (int nt = 0; nt < 8; nt++) s[nt] = make_float4(0.f, 0.f, 0.f, 0.f);
#pragma unroll
        for (int kk = 0; kk < 64; kk += 8) {
            unsigned a0 = f2u(sQ[(rloc + g)     * SQS + kk + t]);
            unsigned a1 = f2u(sQ[(rloc + g + 8) * SQS + kk + t]);
            unsigned a2 = f2u(sQ[(rloc + g)     * SQS + kk + t + 4]);
            unsigned a3 = f2u(sQ[(rloc + g + 8) * SQS + kk + t + 4]);
#pragma unroll
            for (int nt = 0; nt < 8; nt++) {
                unsigned b0 = f2u(sK[(nt * 8 + g) * SKS + kk + t]);
                unsigned b1 = f2u(sK[(nt * 8 + g) * SKS + kk + t + 4]);
                mma_tf32_k8(s[nt], a0, a1, a2, a3, b0, b1);
            }
        }

        const bool diag = (j0 == qm0);
        float mx0 = -CUDART_INF_F, mx1 = -CUDART_INF_F;
#pragma unroll
        for (int nt = 0; nt < 8; nt++) {
            int c = j0 + nt * 8 + t * 2;
            s[nt].x *= 0.125f; s[nt].y *= 0.125f;
            s[nt].z *= 0.125f; s[nt].w *= 0.125f;
            if (diag) {
                if (c     > row0) s[nt].x = -CUDART_INF_F;
                if (c + 1 > row0) s[nt].y = -CUDART_INF_F;
                if (c     > row1) s[nt].z = -CUDART_INF_F;
                if (c + 1 > row1) s[nt].w = -CUDART_INF_F;
            }
            mx0 = fmaxf(mx0, fmaxf(s[nt].x, s[nt].y));
            mx1 = fmaxf(mx1, fmaxf(s[nt].z, s[nt].w));
        }
        mx0 = fmaxf(mx0, __shfl_xor_sync(0xffffffffu, mx0, 1));
        mx0 = fmaxf(mx0, __shfl_xor_sync(0xffffffffu, mx0, 2));
        mx1 = fmaxf(mx1, __shfl_xor_sync(0xffffffffu, mx1, 1));
        mx1 = fmaxf(mx1, __shfl_xor_sync(0xffffffffu, mx1, 2));
        float nm0 = fmaxf(m0, mx0), nm1 = fmaxf(m1, mx1);
        float al0 = __expf(m0 - nm0), al1 = __expf(m1 - nm1);

        float ps0 = 0.f, ps1 = 0.f;
#pragma unroll
        for (int nt = 0; nt < 8; nt++) {
            float p00 = __expf(s[nt].x - nm0), p01 = __expf(s[nt].y - nm0);
            float p10 = __expf(s[nt].z - nm1), p11 = __expf(s[nt].w - nm1);
            ps0 += p00 + p01; ps1 += p10 + p11;
            *(float2*)&sP[(rloc + g)     * SPS + nt * 8 + t * 2] = make_float2(tf32r(p00), tf32r(p01));
            *(float2*)&sP[(rloc + g + 8) * SPS + nt * 8 + t * 2] = make_float2(tf32r(p10), tf32r(p11));
        }
        ps0 += __shfl_xor_sync(0xffffffffu, ps0, 1);
        ps0 += __shfl_xor_sync(0xffffffffu, ps0, 2);
        ps1 += __shfl_xor_sync(0xffffffffu, ps1, 1);
        ps1 += __shfl_xor_sync(0xffffffffu, ps1, 2);
        l0 = l0 * al0 + ps0; l1 = l1 * al1 + ps1;
        m0 = nm0; m1 = nm1;
#pragma unroll
        for (int nt = 0; nt < 8; nt++) {
            oacc[nt].x *= al0; oacc[nt].y *= al0;
            oacc[nt].z *= al1; oacc[nt].w *= al1;
        }
        __syncwarp();

        // O += P @ V (per-warp sP stripe; V is block-shared)
#pragma unroll
        for (int kk = 0; kk < 64; kk += 8) {
            unsigned a0 = f2u(sP[(rloc + g)     * SPS + kk + t]);
            unsigned a1 = f2u(sP[(rloc + g + 8) * SPS + kk + t]);
            unsigned a2 = f2u(sP[(rloc + g)     * SPS + kk + t + 4]);
            unsigned a3 = f2u(sP[(rloc + g + 8) * SPS + kk + t + 4]);
#pragma unroll
            for (int nt = 0; nt < 8; nt++) {
                unsigned b0 = f2u(sV[(kk + t)     * SVS + nt * 8 + g]);
                unsigned b1 = f2u(sV[(kk + t + 4) * SVS + nt * 8 + g]);
                mma_tf32_k8(oacc[nt], a0, a1, a2, a3, b0, b1);
            }
        }
    }

    const float inv0 = 1.f / l0, inv1 = 1.f / l1;
    float* op = o + (size_t)(b * SEQ + row0) * D + h * HK;
#pragma unroll
    for (int nt = 0; nt < 8; nt++) {
        *(float2*)(op + nt * 8 + t * 2) =
            make_float2(oacc[nt].x * inv0, oacc[nt].y * inv0);
        *(float2*)(op + (size_t)8 * D + nt * 8 + t * 2) =
            make_float2(oacc[nt].z * inv1, oacc[nt].w * inv1);
    }
}

// ---------------------------------------------------------------------------
extern "C" void kernel_launch(void* const* d_in, const int* in_sizes, int n_in,
                              void* d_out, int out_size)
{
    const float* x  = (const float*)d_in[0];
    const float* Pi = (const float*)d_in[1];
    const float* Po = (const float*)d_in[2];
    float* y = (float*)d_out;

    float *qkv, *ob;
    cudaGetSymbolAddress((void**)&qkv, g_qkv);
    cudaGetSymbolAddress((void**)&ob,  g_o);

    cudaFuncSetAttribute(flash_tf32, cudaFuncAttributeMaxDynamicSharedMemorySize,
                         ATTN_SMEM);

    gemm_tf32<<<dim3(TD / 128, ROWS / 128), 256>>>(x, Pi, qkv, ROWS, TD, D);
    flash_tf32<<<dim3(SEQ / 64, BATCH * NH), 128, ATTN_SMEM>>>(qkv, ob);
    gemm_tf32<<<dim3(D / 128, ROWS / 128), 256>>>(ob, Po, y, ROWS, D, D);
}